// round 3
// baseline (speedup 1.0000x reference)
#include <cuda_runtime.h>
#include <math.h>

// ---------------------------------------------------------------------------
// Problem constants
// ---------------------------------------------------------------------------
#define S_LEN 1024
#define BATCH 4
#define EMB   1024
#define NH    16
#define HD    64
#define NTOK  (S_LEN * BATCH)     // 4096 tokens, token index t = s*BATCH + b
#define LN_EPS 1e-5f

// ---------------------------------------------------------------------------
// Scratch (device globals -- allocation-free kernel_launch requirement)
// ---------------------------------------------------------------------------
__device__ float g_h  [NTOK * EMB];        // 16 MB  (ln output, reused twice)
__device__ float g_qkv[NTOK * 3 * EMB];    // 48 MB
__device__ float g_a  [NTOK * EMB];        // 16 MB  (attention output, merged heads)
__device__ float g_x2 [NTOK * EMB];        // 16 MB  (x + attn residual)
__device__ float g_m  [NTOK * 4 * EMB];    // 64 MB  (gelu(fc))

// ---------------------------------------------------------------------------
// LayerNorm: one block per row (4096 rows of 1024), 256 threads, 1 float4 each
// ---------------------------------------------------------------------------
__global__ void __launch_bounds__(256) ln_kernel(
    const float* __restrict__ x, const float* __restrict__ gamma,
    const float* __restrict__ beta, float* __restrict__ out)
{
    const int row = blockIdx.x;
    const int t   = threadIdx.x;
    const float4* xr = reinterpret_cast<const float4*>(x + (size_t)row * EMB);
    float4 v = xr[t];

    float s  = v.x + v.y + v.z + v.w;
    float sq = v.x * v.x + v.y * v.y + v.z * v.z + v.w * v.w;
    #pragma unroll
    for (int m = 16; m > 0; m >>= 1) {
        s  += __shfl_xor_sync(0xffffffffu, s,  m);
        sq += __shfl_xor_sync(0xffffffffu, sq, m);
    }

    __shared__ float sh_s[8], sh_q[8];
    __shared__ float sh_mean, sh_rstd;
    const int warp = t >> 5, lane = t & 31;
    if (lane == 0) { sh_s[warp] = s; sh_q[warp] = sq; }
    __syncthreads();
    if (t == 0) {
        float ts = 0.f, tq = 0.f;
        #pragma unroll
        for (int i = 0; i < 8; i++) { ts += sh_s[i]; tq += sh_q[i]; }
        float mean = ts * (1.0f / EMB);
        float var  = tq * (1.0f / EMB) - mean * mean;
        sh_mean = mean;
        sh_rstd = rsqrtf(var + LN_EPS);
    }
    __syncthreads();
    const float mean = sh_mean, rstd = sh_rstd;

    float4 g4 = reinterpret_cast<const float4*>(gamma)[t];
    float4 b4 = reinterpret_cast<const float4*>(beta)[t];
    float4 o;
    o.x = (v.x - mean) * rstd * g4.x + b4.x;
    o.y = (v.y - mean) * rstd * g4.y + b4.y;
    o.z = (v.z - mean) * rstd * g4.z + b4.z;
    o.w = (v.w - mean) * rstd * g4.w + b4.w;
    reinterpret_cast<float4*>(out + (size_t)row * EMB)[t] = o;
}

// ---------------------------------------------------------------------------
// GELU (GPT-2 tanh approximation)
// ---------------------------------------------------------------------------
__device__ __forceinline__ float gelu_f(float x) {
    const float c = 0.7978845608028654f;   // sqrt(2/pi)
    float x3 = x * x * x;
    return 0.5f * x * (1.0f + tanhf(c * (x + 0.044715f * x3)));
}

// ---------------------------------------------------------------------------
// SGEMM: C[M,N] = A[M,K] @ W[K,N] + bias, epilogue:
//   EPI==0 : none
//   EPI==1 : C += res   (residual add, same layout)
//   EPI==2 : C = gelu(C)
// 128x128x8 tiles, 256 threads, 8x8 per thread. All dims multiples of 128/8.
// ---------------------------------------------------------------------------
template <int EPI>
__global__ void __launch_bounds__(256) sgemm_kernel(
    int M, int N, int K,
    const float* __restrict__ A, const float* __restrict__ W,
    const float* __restrict__ bias, const float* __restrict__ res,
    float* __restrict__ C)
{
    constexpr int BM = 128, BN = 128, BK = 8;
    __shared__ float As[BK][BM];
    __shared__ float Bs[BK][BN];

    const int bm = blockIdx.y, bn = blockIdx.x;
    const int t  = threadIdx.x;
    const int tx = t & 15;          // 0..15 -> 8 output cols each
    const int ty = t >> 4;          // 0..15 -> 8 output rows each

    // A tile loaders: 128x8 = 256 float4 -> 1 per thread
    const int ar = t >> 1, ac = (t & 1) << 2;
    // B tile loaders: 8x128 = 256 float4 -> 1 per thread
    const int br = t >> 5, bc = (t & 31) << 2;

    const float* Aptr = A + (size_t)(bm * BM + ar) * K + ac;
    const float* Wptr = W + (size_t)br * N + bn * BN + bc;

    float acc[8][8];
    #pragma unroll
    for (int i = 0; i < 8; i++)
        #pragma unroll
        for (int j = 0; j < 8; j++) acc[i][j] = 0.f;

    for (int k0 = 0; k0 < K; k0 += BK) {
        float4 a4 = *reinterpret_cast<const float4*>(Aptr);
        float4 b4 = *reinterpret_cast<const float4*>(Wptr);
        Aptr += BK;
        Wptr += (size_t)BK * N;

        As[ac + 0][ar] = a4.x;
        As[ac + 1][ar] = a4.y;
        As[ac + 2][ar] = a4.z;
        As[ac + 3][ar] = a4.w;
        *reinterpret_cast<float4*>(&Bs[br][bc]) = b4;
        __syncthreads();

        #pragma unroll
        for (int kk = 0; kk < BK; kk++) {
            float af[8], bfr[8];
            #pragma unroll
            for (int i = 0; i < 8; i++) af[i]  = As[kk][ty * 8 + i];
            #pragma unroll
            for (int j = 0; j < 8; j++) bfr[j] = Bs[kk][tx * 8 + j];
            #pragma unroll
            for (int i = 0; i < 8; i++)
                #pragma unroll
                for (int j = 0; j < 8; j++)
                    acc[i][j] = fmaf(af[i], bfr[j], acc[i][j]);
        }
        __syncthreads();
    }

    const int row0 = bm * BM + ty * 8;
    const int col0 = bn * BN + tx * 8;
    float bv[8];
    #pragma unroll
    for (int j = 0; j < 8; j++) bv[j] = bias[col0 + j];

    #pragma unroll
    for (int i = 0; i < 8; i++) {
        const size_t base = (size_t)(row0 + i) * N + col0;
        float v[8];
        #pragma unroll
        for (int j = 0; j < 8; j++) {
            float o = acc[i][j] + bv[j];
            if (EPI == 1) o += res[base + j];
            if (EPI == 2) o = gelu_f(o);
            v[j] = o;
        }
        *reinterpret_cast<float4*>(C + base)     = make_float4(v[0], v[1], v[2], v[3]);
        *reinterpret_cast<float4*>(C + base + 4) = make_float4(v[4], v[5], v[6], v[7]);
    }
}

// ---------------------------------------------------------------------------
// Flash attention (fp32, no mask): one block per (b,h, 64-row q tile).
// 256 threads; each owns a 4x4 tile of the 64x64 score block AND a 4x4
// (rows x head-dims) tile of the output. Online softmax with running m/l.
// qkv layout: [t = s*BATCH+b][ q(1024) | k(1024) | v(1024) ], head h at h*64.
// Output a[t][h*64 + d]  (merged heads, token layout -> direct proj GEMM).
// ---------------------------------------------------------------------------
#define QS_STRIDE (HD + 1)        // padded: fixed-column reads across rows
#define PS_STRIDE (64 + 1)
#define ATTN_SMEM_FLOATS (64 * QS_STRIDE /*Q*/ + 64 * QS_STRIDE /*K*/ + \
                          64 * PS_STRIDE /*P*/ + 64 * HD /*V*/)
#define ATTN_SMEM_BYTES  (ATTN_SMEM_FLOATS * 4)

__global__ void __launch_bounds__(256) attn_kernel(
    const float* __restrict__ qkv, float* __restrict__ out)
{
    extern __shared__ float sm[];
    float* Qs = sm;                       // [64][QS_STRIDE]
    float* Ks = Qs + 64 * QS_STRIDE;      // [64][QS_STRIDE]
    float* Ps = Ks + 64 * QS_STRIDE;      // [64][PS_STRIDE]
    float* Vs = Ps + 64 * PS_STRIDE;      // [64][HD]  (row-wise reads, no pad)

    const int bh = blockIdx.x;
    const int b  = bh / NH;
    const int h  = bh % NH;
    const int q0 = blockIdx.y * 64;

    const int t  = threadIdx.x;
    const int tr = t >> 4;                // 0..15
    const int tc = t & 15;                // 0..15
    const int r0 = tr * 4, c0 = tc * 4;

    // Load Q tile (64 rows x 64 dims) -- 4 float4 per thread
    #pragma unroll
    for (int i = 0; i < 4; i++) {
        const int idx = t + i * 256;      // 0..1023
        const int r   = idx >> 4;
        const int c   = (idx & 15) << 2;
        const float4 v = *reinterpret_cast<const float4*>(
            qkv + (size_t)((q0 + r) * BATCH + b) * (3 * EMB) + h * HD + c);
        Qs[r * QS_STRIDE + c + 0] = v.x;
        Qs[r * QS_STRIDE + c + 1] = v.y;
        Qs[r * QS_STRIDE + c + 2] = v.z;
        Qs[r * QS_STRIDE + c + 3] = v.w;
    }

    float mrow[4], lrow[4], o[4][4];
    #pragma unroll
    for (int r = 0; r < 4; r++) {
        mrow[r] = -1e30f; lrow[r] = 0.f;
        #pragma unroll
        for (int c = 0; c < 4; c++) o[r][c] = 0.f;
    }

    for (int kt = 0; kt < S_LEN; kt += 64) {
        __syncthreads();   // previous iteration's smem reads complete
        #pragma unroll
        for (int i = 0; i < 4; i++) {
            const int idx = t + i * 256;
            const int r   = idx >> 4;
            const int c   = (idx & 15) << 2;
            const size_t base =
                (size_t)((kt + r) * BATCH + b) * (3 * EMB) + h * HD + c;
            const float4 kv = *reinterpret_cast<const float4*>(qkv + base + EMB);
            const float4 vv = *reinterpret_cast<const float4*>(qkv + base + 2 * EMB);
            Ks[r * QS_STRIDE + c + 0] = kv.x;
            Ks[r * QS_STRIDE + c + 1] = kv.y;
            Ks[r * QS_STRIDE + c + 2] = kv.z;
            Ks[r * QS_STRIDE + c + 3] = kv.w;
            *reinterpret_cast<float4*>(&Vs[r * HD + c]) = vv;
        }
        __syncthreads();

        // ---- scores: 4x4 per thread over the 64x64 tile ----
        float sacc[4][4];
        #pragma unroll
        for (int r = 0; r < 4; r++)
            #pragma unroll
            for (int c = 0; c < 4; c++) sacc[r][c] = 0.f;

        #pragma unroll 8
        for (int kk = 0; kk < HD; kk++) {
            float qv[4], kv[4];
            #pragma unroll
            for (int r = 0; r < 4; r++) qv[r] = Qs[(r0 + r) * QS_STRIDE + kk];
            #pragma unroll
            for (int c = 0; c < 4; c++) kv[c] = Ks[(c0 + c) * QS_STRIDE + kk];
            #pragma unroll
            for (int r = 0; r < 4; r++)
                #pragma unroll
                for (int c = 0; c < 4; c++)
                    sacc[r][c] = fmaf(qv[r], kv[c], sacc[r][c]);
        }

        // ---- online softmax per row (16-lane groups share a row set) ----
        #pragma unroll
        for (int r = 0; r < 4; r++) {
            float tmax = -1e30f;
            #pragma unroll
            for (int c = 0; c < 4; c++) {
                sacc[r][c] *= 0.125f;                 // 1/sqrt(64)
                tmax = fmaxf(tmax, sacc[r][c]);
            }
            #pragma unroll
            for (int msk = 1; msk < 16; msk <<= 1)
                tmax = fmaxf(tmax, __shfl_xor_sync(0xffffffffu, tmax, msk));

            const float mnew  = fmaxf(mrow[r], tmax);
            const float alpha = __expf(mrow[r] - mnew);
            float tsum = 0.f;
            #pragma unroll
            for (int c = 0; c < 4; c++) {
                const float p = __expf(sacc[r][c] - mnew);
                Ps[(r0 + r) * PS_STRIDE + c0 + c] = p;
                tsum += p;
            }
            #pragma unroll
            for (int msk = 1; msk < 16; msk <<= 1)
                tsum += __shfl_xor_sync(0xffffffffu, tsum, msk);

            lrow[r] = lrow[r] * alpha + tsum;
            mrow[r] = mnew;
            #pragma unroll
            for (int c = 0; c < 4; c++) o[r][c] *= alpha;
        }
        __syncwarp();   // P row is produced+consumed within one warp

        // ---- AV: o[r][d] += sum_j P[r][j] * V[j][d], d = c0..c0+3 ----
        #pragma unroll 8
        for (int j = 0; j < 64; j++) {
            float pv[4], vv[4];
            #pragma unroll
            for (int r = 0; r < 4; r++) pv[r] = Ps[(r0 + r) * PS_STRIDE + j];
            #pragma unroll
            for (int c = 0; c < 4; c++) vv[c] = Vs[j * HD + c0 + c];
            #pragma unroll
            for (int r = 0; r < 4; r++)
                #pragma unroll
                for (int c = 0; c < 4; c++)
                    o[r][c] = fmaf(pv[r], vv[c], o[r][c]);
        }
    }

    // ---- finalize and store ----
    #pragma unroll
    for (int r = 0; r < 4; r++) {
        const float inv = 1.0f / lrow[r];
        const int s = q0 + r0 + r;
        float* dst = out + (size_t)(s * BATCH + b) * EMB + h * HD + c0;
        *reinterpret_cast<float4*>(dst) =
            make_float4(o[r][0] * inv, o[r][1] * inv, o[r][2] * inv, o[r][3] * inv);
    }
}

// ---------------------------------------------------------------------------
// Launch
// ---------------------------------------------------------------------------
extern "C" void kernel_launch(void* const* d_in, const int* in_sizes, int n_in,
                              void* d_out, int out_size)
{
    const float* x      = (const float*)d_in[0];
    const float* ln1_g  = (const float*)d_in[1];
    const float* ln1_b  = (const float*)d_in[2];
    const float* w_attn = (const float*)d_in[3];
    const float* b_attn = (const float*)d_in[4];
    const float* w_proj = (const float*)d_in[5];
    const float* b_proj = (const float*)d_in[6];
    const float* ln2_g  = (const float*)d_in[7];
    const float* ln2_b  = (const float*)d_in[8];
    const float* w_fc   = (const float*)d_in[9];
    const float* b_fc   = (const float*)d_in[10];
    const float* w_out  = (const float*)d_in[11];
    const float* b_out  = (const float*)d_in[12];
    float* out = (float*)d_out;

    void *p_h, *p_qkv, *p_a, *p_x2, *p_m;
    cudaGetSymbolAddress(&p_h,   g_h);
    cudaGetSymbolAddress(&p_qkv, g_qkv);
    cudaGetSymbolAddress(&p_a,   g_a);
    cudaGetSymbolAddress(&p_x2,  g_x2);
    cudaGetSymbolAddress(&p_m,   g_m);
    float* h   = (float*)p_h;
    float* qkv = (float*)p_qkv;
    float* a   = (float*)p_a;
    float* x2  = (float*)p_x2;
    float* mm  = (float*)p_m;

    cudaFuncSetAttribute(attn_kernel,
                         cudaFuncAttributeMaxDynamicSharedMemorySize,
                         ATTN_SMEM_BYTES);

    // 1. ln1
    ln_kernel<<<NTOK, 256>>>(x, ln1_g, ln1_b, h);
    // 2. qkv = h @ w_attn + b_attn            [4096, 3072]
    sgemm_kernel<0><<<dim3(3 * EMB / 128, NTOK / 128), 256>>>(
        NTOK, 3 * EMB, EMB, h, w_attn, b_attn, nullptr, qkv);
    // 3. attention -> a (merged heads, token layout)
    attn_kernel<<<dim3(BATCH * NH, S_LEN / 64), 256, ATTN_SMEM_BYTES>>>(qkv, a);
    // 4. x2 = x + a @ w_proj + b_proj
    sgemm_kernel<1><<<dim3(EMB / 128, NTOK / 128), 256>>>(
        NTOK, EMB, EMB, a, w_proj, b_proj, x, x2);
    // 5. ln2
    ln_kernel<<<NTOK, 256>>>(x2, ln2_g, ln2_b, h);
    // 6. m = gelu(h @ w_fc + b_fc)            [4096, 4096]
    sgemm_kernel<2><<<dim3(4 * EMB / 128, NTOK / 128), 256>>>(
        NTOK, 4 * EMB, EMB, h, w_fc, b_fc, nullptr, mm);
    // 7. out = x2 + m @ w_out + b_out
    sgemm_kernel<1><<<dim3(EMB / 128, NTOK / 128), 256>>>(
        NTOK, EMB, 4 * EMB, mm, w_out, b_out, x2, out);
}

// round 4
// speedup vs baseline: 2.3758x; 2.3758x over previous
#include <cuda_runtime.h>
#include <math.h>
#include <stdint.h>

// ---------------------------------------------------------------------------
// Problem constants
// ---------------------------------------------------------------------------
#define S_LEN 1024
#define BATCH 4
#define EMB   1024
#define NH    16
#define HD    64
#define NTOK  (S_LEN * BATCH)     // 4096 tokens, token index t = s*BATCH + b
#define LN_EPS 1e-5f

// ---------------------------------------------------------------------------
// Scratch (device globals -- allocation-free kernel_launch requirement)
// ---------------------------------------------------------------------------
__device__ float g_h  [NTOK * EMB];        // 16 MB  (ln output, reused twice)
__device__ float g_qkv[NTOK * 3 * EMB];    // 48 MB
__device__ float g_a  [NTOK * EMB];        // 16 MB  (attention out, merged heads)
__device__ float g_x2 [NTOK * EMB];        // 16 MB  (x + attn residual)
__device__ float g_m  [NTOK * 4 * EMB];    // 64 MB  (gelu(fc))

// ---------------------------------------------------------------------------
// LayerNorm: one block per row (4096 rows of 1024), 256 threads, 1 float4 each
// ---------------------------------------------------------------------------
__global__ void __launch_bounds__(256) ln_kernel(
    const float* __restrict__ x, const float* __restrict__ gamma,
    const float* __restrict__ beta, float* __restrict__ out)
{
    const int row = blockIdx.x;
    const int t   = threadIdx.x;
    const float4* xr = reinterpret_cast<const float4*>(x + (size_t)row * EMB);
    float4 v = xr[t];

    float s  = v.x + v.y + v.z + v.w;
    float sq = v.x * v.x + v.y * v.y + v.z * v.z + v.w * v.w;
    #pragma unroll
    for (int m = 16; m > 0; m >>= 1) {
        s  += __shfl_xor_sync(0xffffffffu, s,  m);
        sq += __shfl_xor_sync(0xffffffffu, sq, m);
    }

    __shared__ float sh_s[8], sh_q[8];
    __shared__ float sh_mean, sh_rstd;
    const int warp = t >> 5, lane = t & 31;
    if (lane == 0) { sh_s[warp] = s; sh_q[warp] = sq; }
    __syncthreads();
    if (t == 0) {
        float ts = 0.f, tq = 0.f;
        #pragma unroll
        for (int i = 0; i < 8; i++) { ts += sh_s[i]; tq += sh_q[i]; }
        float mean = ts * (1.0f / EMB);
        float var  = tq * (1.0f / EMB) - mean * mean;
        sh_mean = mean;
        sh_rstd = rsqrtf(var + LN_EPS);
    }
    __syncthreads();
    const float mean = sh_mean, rstd = sh_rstd;

    float4 g4 = reinterpret_cast<const float4*>(gamma)[t];
    float4 b4 = reinterpret_cast<const float4*>(beta)[t];
    float4 o;
    o.x = (v.x - mean) * rstd * g4.x + b4.x;
    o.y = (v.y - mean) * rstd * g4.y + b4.y;
    o.z = (v.z - mean) * rstd * g4.z + b4.z;
    o.w = (v.w - mean) * rstd * g4.w + b4.w;
    reinterpret_cast<float4*>(out + (size_t)row * EMB)[t] = o;
}

// ---------------------------------------------------------------------------
// GELU (GPT-2 tanh approximation)
// ---------------------------------------------------------------------------
__device__ __forceinline__ float gelu_f(float x) {
    const float c = 0.7978845608028654f;   // sqrt(2/pi)
    float x3 = x * x * x;
    return 0.5f * x * (1.0f + tanhf(c * (x + 0.044715f * x3)));
}

// ---------------------------------------------------------------------------
// TF32 helpers
// ---------------------------------------------------------------------------
__device__ __forceinline__ uint32_t f2tf32(float x) {
    uint32_t u;
    asm("cvt.rna.tf32.f32 %0, %1;" : "=r"(u) : "f"(x));
    return u;
}

__device__ __forceinline__ void mma_tf32(
    float c[4], const uint32_t a[4], const uint32_t b[2])
{
    asm volatile(
        "mma.sync.aligned.m16n8k8.row.col.f32.tf32.tf32.f32 "
        "{%0,%1,%2,%3}, {%4,%5,%6,%7}, {%8,%9}, {%0,%1,%2,%3};\n"
        : "+f"(c[0]), "+f"(c[1]), "+f"(c[2]), "+f"(c[3])
        : "r"(a[0]), "r"(a[1]), "r"(a[2]), "r"(a[3]),
          "r"(b[0]), "r"(b[1]));
}

// ---------------------------------------------------------------------------
// TF32 tensor-core GEMM: C[M,N] = A[M,K] @ W[K,N] + bias, epilogue:
//   EPI==0 : none    EPI==1 : C += res    EPI==2 : C = gelu(C)
// 128x128x32 block tile, 8 warps, 64x32 warp tile, m16n8k8 mma,
// double-buffered smem, fp32->tf32 conversion at smem-store time.
// M,N multiples of 128; K multiple of 32.
// ---------------------------------------------------------------------------
#define GAST 36                         // As row stride (in u32): [m][k] padded
#define GBST 136                        // Bs row stride (in u32): [k][n] padded
#define GASZ (128 * GAST)               // 4608 u32 per buffer
#define GBSZ (32 * GBST)                // 4352 u32 per buffer
#define GEMM_SMEM_BYTES ((2 * (GASZ + GBSZ)) * 4)   // 71680 B

template <int EPI>
__global__ void __launch_bounds__(256) gemm_tf32(
    int M, int N, int K,
    const float* __restrict__ A, const float* __restrict__ W,
    const float* __restrict__ bias, const float* __restrict__ res,
    float* __restrict__ C)
{
    extern __shared__ uint32_t smem_u[];
    uint32_t* AsBase = smem_u;               // [2][GASZ]
    uint32_t* BsBase = smem_u + 2 * GASZ;    // [2][GBSZ]

    const int bm = blockIdx.y, bn = blockIdx.x;
    const int t    = threadIdx.x;
    const int warp = t >> 5, lane = t & 31;
    const int wm = warp >> 2;               // 0..1 : 64-row slab
    const int wn = warp & 3;                // 0..3 : 32-col slab
    const int g  = lane >> 2;               // 0..7
    const int q  = lane & 3;                // 0..3

    float acc[4][4][4];
    #pragma unroll
    for (int mi = 0; mi < 4; mi++)
        #pragma unroll
        for (int ni = 0; ni < 4; ni++)
            #pragma unroll
            for (int j = 0; j < 4; j++) acc[mi][ni][j] = 0.f;

    float4 abuf[4], bbuf[4];

    // A stage: 128x32 fp32 = 1024 float4; idx = t + i*256; row=idx>>3, c4=idx&7
    // B stage: 32x128 fp32 = 1024 float4; row=idx>>5, c4=idx&31
    #define LOAD_A(k0)                                                         \
        {                                                                      \
            _Pragma("unroll")                                                  \
            for (int i = 0; i < 4; i++) {                                      \
                int idx = t + i * 256;                                         \
                int r = idx >> 3, c = (idx & 7) << 2;                          \
                abuf[i] = *reinterpret_cast<const float4*>(                    \
                    A + (size_t)(bm * 128 + r) * K + (k0) + c);                \
            }                                                                  \
        }
    #define LOAD_B(k0)                                                         \
        {                                                                      \
            _Pragma("unroll")                                                  \
            for (int i = 0; i < 4; i++) {                                      \
                int idx = t + i * 256;                                         \
                int r = idx >> 5, c = (idx & 31) << 2;                         \
                bbuf[i] = *reinterpret_cast<const float4*>(                    \
                    W + (size_t)((k0) + r) * N + bn * 128 + c);                \
            }                                                                  \
        }
    #define STORE_AB(bufsel)                                                   \
        {                                                                      \
            uint32_t* as = AsBase + (bufsel) * GASZ;                           \
            uint32_t* bs = BsBase + (bufsel) * GBSZ;                           \
            _Pragma("unroll")                                                  \
            for (int i = 0; i < 4; i++) {                                      \
                int idx = t + i * 256;                                         \
                int r = idx >> 3, c = (idx & 7) << 2;                          \
                uint32_t* p = as + r * GAST + c;                               \
                p[0] = f2tf32(abuf[i].x); p[1] = f2tf32(abuf[i].y);            \
                p[2] = f2tf32(abuf[i].z); p[3] = f2tf32(abuf[i].w);            \
            }                                                                  \
            _Pragma("unroll")                                                  \
            for (int i = 0; i < 4; i++) {                                      \
                int idx = t + i * 256;                                         \
                int r = idx >> 5, c = (idx & 31) << 2;                         \
                uint32_t* p = bs + r * GBST + c;                               \
                p[0] = f2tf32(bbuf[i].x); p[1] = f2tf32(bbuf[i].y);            \
                p[2] = f2tf32(bbuf[i].z); p[3] = f2tf32(bbuf[i].w);            \
            }                                                                  \
        }

    LOAD_A(0); LOAD_B(0);
    STORE_AB(0);
    __syncthreads();

    int buf = 0;
    for (int k0 = 32; ; k0 += 32) {
        const bool more = (k0 < K);
        if (more) { LOAD_A(k0); LOAD_B(k0); }

        // ---- compute on current buffer ----
        {
            const uint32_t* as = AsBase + buf * GASZ + (wm * 64 + g) * GAST;
            const uint32_t* bs = BsBase + buf * GBSZ + wn * 32 + g;
            #pragma unroll
            for (int ks = 0; ks < 4; ks++) {
                const int kk = ks * 8;
                uint32_t af[4][4], bf[4][2];
                #pragma unroll
                for (int mi = 0; mi < 4; mi++) {
                    const uint32_t* p = as + mi * 16 * GAST + kk + q;
                    af[mi][0] = p[0];
                    af[mi][1] = p[8 * GAST];
                    af[mi][2] = p[4];
                    af[mi][3] = p[8 * GAST + 4];
                }
                #pragma unroll
                for (int ni = 0; ni < 4; ni++) {
                    const uint32_t* p = bs + (kk + q) * GBST + ni * 8;
                    bf[ni][0] = p[0];
                    bf[ni][1] = p[4 * GBST];
                }
                #pragma unroll
                for (int mi = 0; mi < 4; mi++)
                    #pragma unroll
                    for (int ni = 0; ni < 4; ni++)
                        mma_tf32(acc[mi][ni], af[mi], bf[ni]);
            }
        }

        if (!more) break;
        STORE_AB(buf ^ 1);
        __syncthreads();
        buf ^= 1;
    }

    // ---- epilogue ----
    const int row_base = bm * 128 + wm * 64;
    const int col_base = bn * 128 + wn * 32;
    #pragma unroll
    for (int mi = 0; mi < 4; mi++) {
        #pragma unroll
        for (int ni = 0; ni < 4; ni++) {
            const int col = col_base + ni * 8 + 2 * q;
            const float b0 = bias[col], b1 = bias[col + 1];
            #pragma unroll
            for (int half = 0; half < 2; half++) {
                const int row = row_base + mi * 16 + g + half * 8;
                const size_t base = (size_t)row * N + col;
                float v0 = acc[mi][ni][half * 2 + 0] + b0;
                float v1 = acc[mi][ni][half * 2 + 1] + b1;
                if (EPI == 1) { v0 += res[base]; v1 += res[base + 1]; }
                if (EPI == 2) { v0 = gelu_f(v0); v1 = gelu_f(v1); }
                *reinterpret_cast<float2*>(C + base) = make_float2(v0, v1);
            }
        }
    }
    #undef LOAD_A
    #undef LOAD_B
    #undef STORE_AB
}

// ---------------------------------------------------------------------------
// Flash attention (fp32, no mask): one block per (b,h, 64-row q tile).
// ---------------------------------------------------------------------------
#define QS_STRIDE (HD + 1)
#define PS_STRIDE (64 + 1)
#define ATTN_SMEM_FLOATS (64 * QS_STRIDE + 64 * QS_STRIDE + \
                          64 * PS_STRIDE + 64 * HD)
#define ATTN_SMEM_BYTES  (ATTN_SMEM_FLOATS * 4)

__global__ void __launch_bounds__(256) attn_kernel(
    const float* __restrict__ qkv, float* __restrict__ out)
{
    extern __shared__ float sm[];
    float* Qs = sm;
    float* Ks = Qs + 64 * QS_STRIDE;
    float* Ps = Ks + 64 * QS_STRIDE;
    float* Vs = Ps + 64 * PS_STRIDE;

    const int bh = blockIdx.x;
    const int b  = bh / NH;
    const int h  = bh % NH;
    const int q0 = blockIdx.y * 64;

    const int t  = threadIdx.x;
    const int tr = t >> 4;
    const int tc = t & 15;
    const int r0 = tr * 4, c0 = tc * 4;

    #pragma unroll
    for (int i = 0; i < 4; i++) {
        const int idx = t + i * 256;
        const int r   = idx >> 4;
        const int c   = (idx & 15) << 2;
        const float4 v = *reinterpret_cast<const float4*>(
            qkv + (size_t)((q0 + r) * BATCH + b) * (3 * EMB) + h * HD + c);
        Qs[r * QS_STRIDE + c + 0] = v.x;
        Qs[r * QS_STRIDE + c + 1] = v.y;
        Qs[r * QS_STRIDE + c + 2] = v.z;
        Qs[r * QS_STRIDE + c + 3] = v.w;
    }

    float mrow[4], lrow[4], o[4][4];
    #pragma unroll
    for (int r = 0; r < 4; r++) {
        mrow[r] = -1e30f; lrow[r] = 0.f;
        #pragma unroll
        for (int c = 0; c < 4; c++) o[r][c] = 0.f;
    }

    for (int kt = 0; kt < S_LEN; kt += 64) {
        __syncthreads();
        #pragma unroll
        for (int i = 0; i < 4; i++) {
            const int idx = t + i * 256;
            const int r   = idx >> 4;
            const int c   = (idx & 15) << 2;
            const size_t base =
                (size_t)((kt + r) * BATCH + b) * (3 * EMB) + h * HD + c;
            const float4 kv = *reinterpret_cast<const float4*>(qkv + base + EMB);
            const float4 vv = *reinterpret_cast<const float4*>(qkv + base + 2 * EMB);
            Ks[r * QS_STRIDE + c + 0] = kv.x;
            Ks[r * QS_STRIDE + c + 1] = kv.y;
            Ks[r * QS_STRIDE + c + 2] = kv.z;
            Ks[r * QS_STRIDE + c + 3] = kv.w;
            *reinterpret_cast<float4*>(&Vs[r * HD + c]) = vv;
        }
        __syncthreads();

        float sacc[4][4];
        #pragma unroll
        for (int r = 0; r < 4; r++)
            #pragma unroll
            for (int c = 0; c < 4; c++) sacc[r][c] = 0.f;

        #pragma unroll 8
        for (int kk = 0; kk < HD; kk++) {
            float qv[4], kv[4];
            #pragma unroll
            for (int r = 0; r < 4; r++) qv[r] = Qs[(r0 + r) * QS_STRIDE + kk];
            #pragma unroll
            for (int c = 0; c < 4; c++) kv[c] = Ks[(c0 + c) * QS_STRIDE + kk];
            #pragma unroll
            for (int r = 0; r < 4; r++)
                #pragma unroll
                for (int c = 0; c < 4; c++)
                    sacc[r][c] = fmaf(qv[r], kv[c], sacc[r][c]);
        }

        #pragma unroll
        for (int r = 0; r < 4; r++) {
            float tmax = -1e30f;
            #pragma unroll
            for (int c = 0; c < 4; c++) {
                sacc[r][c] *= 0.125f;
                tmax = fmaxf(tmax, sacc[r][c]);
            }
            #pragma unroll
            for (int msk = 1; msk < 16; msk <<= 1)
                tmax = fmaxf(tmax, __shfl_xor_sync(0xffffffffu, tmax, msk));

            const float mnew  = fmaxf(mrow[r], tmax);
            const float alpha = __expf(mrow[r] - mnew);
            float tsum = 0.f;
            #pragma unroll
            for (int c = 0; c < 4; c++) {
                const float p = __expf(sacc[r][c] - mnew);
                Ps[(r0 + r) * PS_STRIDE + c0 + c] = p;
                tsum += p;
            }
            #pragma unroll
            for (int msk = 1; msk < 16; msk <<= 1)
                tsum += __shfl_xor_sync(0xffffffffu, tsum, msk);

            lrow[r] = lrow[r] * alpha + tsum;
            mrow[r] = mnew;
            #pragma unroll
            for (int c = 0; c < 4; c++) o[r][c] *= alpha;
        }
        __syncwarp();

        #pragma unroll 8
        for (int j = 0; j < 64; j++) {
            float pv[4], vv[4];
            #pragma unroll
            for (int r = 0; r < 4; r++) pv[r] = Ps[(r0 + r) * PS_STRIDE + j];
            #pragma unroll
            for (int c = 0; c < 4; c++) vv[c] = Vs[j * HD + c0 + c];
            #pragma unroll
            for (int r = 0; r < 4; r++)
                #pragma unroll
                for (int c = 0; c < 4; c++)
                    o[r][c] = fmaf(pv[r], vv[c], o[r][c]);
        }
    }

    #pragma unroll
    for (int r = 0; r < 4; r++) {
        const float inv = 1.0f / lrow[r];
        const int s = q0 + r0 + r;
        float* dst = out + (size_t)(s * BATCH + b) * EMB + h * HD + c0;
        *reinterpret_cast<float4*>(dst) =
            make_float4(o[r][0] * inv, o[r][1] * inv, o[r][2] * inv, o[r][3] * inv);
    }
}

// ---------------------------------------------------------------------------
// Launch
// ---------------------------------------------------------------------------
extern "C" void kernel_launch(void* const* d_in, const int* in_sizes, int n_in,
                              void* d_out, int out_size)
{
    const float* x      = (const float*)d_in[0];
    const float* ln1_g  = (const float*)d_in[1];
    const float* ln1_b  = (const float*)d_in[2];
    const float* w_attn = (const float*)d_in[3];
    const float* b_attn = (const float*)d_in[4];
    const float* w_proj = (const float*)d_in[5];
    const float* b_proj = (const float*)d_in[6];
    const float* ln2_g  = (const float*)d_in[7];
    const float* ln2_b  = (const float*)d_in[8];
    const float* w_fc   = (const float*)d_in[9];
    const float* b_fc   = (const float*)d_in[10];
    const float* w_out  = (const float*)d_in[11];
    const float* b_out  = (const float*)d_in[12];
    float* out = (float*)d_out;

    void *p_h, *p_qkv, *p_a, *p_x2, *p_m;
    cudaGetSymbolAddress(&p_h,   g_h);
    cudaGetSymbolAddress(&p_qkv, g_qkv);
    cudaGetSymbolAddress(&p_a,   g_a);
    cudaGetSymbolAddress(&p_x2,  g_x2);
    cudaGetSymbolAddress(&p_m,   g_m);
    float* h   = (float*)p_h;
    float* qkv = (float*)p_qkv;
    float* a   = (float*)p_a;
    float* x2  = (float*)p_x2;
    float* mm  = (float*)p_m;

    cudaFuncSetAttribute(attn_kernel,
                         cudaFuncAttributeMaxDynamicSharedMemorySize,
                         ATTN_SMEM_BYTES);
    cudaFuncSetAttribute(gemm_tf32<0>,
                         cudaFuncAttributeMaxDynamicSharedMemorySize,
                         GEMM_SMEM_BYTES);
    cudaFuncSetAttribute(gemm_tf32<1>,
                         cudaFuncAttributeMaxDynamicSharedMemorySize,
                         GEMM_SMEM_BYTES);
    cudaFuncSetAttribute(gemm_tf32<2>,
                         cudaFuncAttributeMaxDynamicSharedMemorySize,
                         GEMM_SMEM_BYTES);

    // 1. ln1
    ln_kernel<<<NTOK, 256>>>(x, ln1_g, ln1_b, h);
    // 2. qkv = h @ w_attn + b_attn            [4096, 3072]
    gemm_tf32<0><<<dim3(3 * EMB / 128, NTOK / 128), 256, GEMM_SMEM_BYTES>>>(
        NTOK, 3 * EMB, EMB, h, w_attn, b_attn, nullptr, qkv);
    // 3. attention -> a (merged heads, token layout)
    attn_kernel<<<dim3(BATCH * NH, S_LEN / 64), 256, ATTN_SMEM_BYTES>>>(qkv, a);
    // 4. x2 = x + a @ w_proj + b_proj
    gemm_tf32<1><<<dim3(EMB / 128, NTOK / 128), 256, GEMM_SMEM_BYTES>>>(
        NTOK, EMB, EMB, a, w_proj, b_proj, x, x2);
    // 5. ln2
    ln_kernel<<<NTOK, 256>>>(x2, ln2_g, ln2_b, h);
    // 6. m = gelu(h @ w_fc + b_fc)            [4096, 4096]
    gemm_tf32<2><<<dim3(4 * EMB / 128, NTOK / 128), 256, GEMM_SMEM_BYTES>>>(
        NTOK, 4 * EMB, EMB, h, w_fc, b_fc, nullptr, mm);
    // 7. out = x2 + m @ w_out + b_out
    gemm_tf32<1><<<dim3(EMB / 128, NTOK / 128), 256, GEMM_SMEM_BYTES>>>(
        NTOK, EMB, 4 * EMB, mm, w_out, b_out, x2, out);
}